// round 17
// baseline (speedup 1.0000x reference)
#include <cuda_runtime.h>
#include <cuda_bf16.h>
#include <math.h>

// B=16, S=128, N=64, E=DK=H=128, L=32

__device__ float g_Xg[2*16*128*512];
__device__ float g_Xl[2*16*128*128];
__device__ float g_Wg[2*16*64*384];
__device__ float g_feats[16*128*256];
__device__ float g_logits[16*128*32];
__device__ float g_res[16];
__device__ float g_ch[32][129*128];           // c history per (dir,b), fp32
__device__ unsigned g_Wch_bf[2][128*256];     // bf16x2 packed [dir][k][colpair]
__device__ unsigned g_Wlc_bf[2][128*64];      // bf16x2 packed [dir][k][colpair]

__device__ __forceinline__ float sigm(float x) { return 1.f / (1.f + expf(-x)); }

// ---------------- weight conversion: fp32 -> packed bf16x2, [k][colpair] ----------------
__global__ void convert_weights_kernel(const float* __restrict__ f_Wch, const float* __restrict__ r_Wch,
                                       const float* __restrict__ f_Wlc, const float* __restrict__ r_Wlc)
{
    int i = blockIdx.x * 256 + threadIdx.x;
    // Wch: [128][512] -> [128][256] pairs
    if (i < 2 * 128 * 256) {
        int dir = i >= 128 * 256;
        int r = i - dir * 128 * 256;
        int k = r >> 8, cp = r & 255;
        const float* W = dir ? r_Wch : f_Wch;
        __nv_bfloat16 lo = __float2bfloat16(W[(size_t)k * 512 + 2 * cp]);
        __nv_bfloat16 hi = __float2bfloat16(W[(size_t)k * 512 + 2 * cp + 1]);
        unsigned u = ((unsigned)__bfloat16_as_ushort(hi) << 16) | __bfloat16_as_ushort(lo);
        g_Wch_bf[dir][r] = u;
    }
    // Wlc: [128][128] -> [128][64] pairs
    if (i < 2 * 128 * 64) {
        int dir = i >= 128 * 64;
        int r = i - dir * 128 * 64;
        int k = r >> 6, cp = r & 63;
        const float* W = dir ? r_Wlc : f_Wlc;
        __nv_bfloat16 lo = __float2bfloat16(W[(size_t)k * 128 + 2 * cp]);
        __nv_bfloat16 hi = __float2bfloat16(W[(size_t)k * 128 + 2 * cp + 1]);
        unsigned u = ((unsigned)__bfloat16_as_ushort(hi) << 16) | __bfloat16_as_ushort(lo);
        g_Wlc_bf[dir][r] = u;
    }
}

// ---------------- precompute GEMMs with embedding gather ----------------
__global__ void gemm_gather_kernel(int mode,
    const int* __restrict__ char_ids, const int* __restrict__ kb_ids,
    const float* __restrict__ char_emb, const float* __restrict__ kb_emb,
    const float* __restrict__ Wf, const float* __restrict__ Wr,
    const float* __restrict__ bf, const float* __restrict__ br,
    int C, int rows_per_dir)
{
    __shared__ float As[64 * 128];
    __shared__ float Wsm[32 * 64];
    __shared__ int ids[64];
    int tid = threadIdx.x;
    int c0 = blockIdx.x * 64;
    int r0 = blockIdx.y * 64;
    int dir = (r0 >= rows_per_dir) ? 1 : 0;
    float* out = (mode == 0) ? g_Xg : (mode == 1) ? g_Xl : g_Wg;
    const float* emb = (mode == 2) ? kb_emb : char_emb;
    if (tid < 64) {
        int r = r0 + tid, id;
        if (mode < 2) {
            int t = r & 127, b = (r >> 7) & 15;
            int pos = dir ? (127 - t) : t;
            id = char_ids[b * 128 + pos];
        } else {
            int w = r & 63, b = (r >> 6) & 15;
            id = kb_ids[b * 64 + w];
        }
        ids[tid] = id;
    }
    __syncthreads();
    for (int i = tid; i < 64 * 32; i += 256) {
        int row = i >> 5, q = i & 31;
        float4 v = reinterpret_cast<const float4*>(emb + (size_t)ids[row] * 128)[q];
        reinterpret_cast<float4*>(As + row * 128)[q] = v;
    }
    const float* W = dir ? Wr : Wf;
    const float* bias = dir ? br : bf;
    int tx = tid & 15, ty = tid >> 4;
    float acc[4][4] = {};
    for (int kc = 0; kc < 4; ++kc) {
        __syncthreads();
        for (int i = tid; i < 2048; i += 256) {
            int kk = i >> 6, cc = i & 63;
            Wsm[i] = W[(size_t)(kc * 32 + kk) * C + c0 + cc];
        }
        __syncthreads();
        #pragma unroll 8
        for (int kk = 0; kk < 32; ++kk) {
            float a0 = As[(ty*4+0)*128 + kc*32+kk], a1 = As[(ty*4+1)*128 + kc*32+kk];
            float a2 = As[(ty*4+2)*128 + kc*32+kk], a3 = As[(ty*4+3)*128 + kc*32+kk];
            float w0 = Wsm[kk*64+tx*4], w1 = Wsm[kk*64+tx*4+1];
            float w2 = Wsm[kk*64+tx*4+2], w3 = Wsm[kk*64+tx*4+3];
            acc[0][0]=fmaf(a0,w0,acc[0][0]); acc[0][1]=fmaf(a0,w1,acc[0][1]);
            acc[0][2]=fmaf(a0,w2,acc[0][2]); acc[0][3]=fmaf(a0,w3,acc[0][3]);
            acc[1][0]=fmaf(a1,w0,acc[1][0]); acc[1][1]=fmaf(a1,w1,acc[1][1]);
            acc[1][2]=fmaf(a1,w2,acc[1][2]); acc[1][3]=fmaf(a1,w3,acc[1][3]);
            acc[2][0]=fmaf(a2,w0,acc[2][0]); acc[2][1]=fmaf(a2,w1,acc[2][1]);
            acc[2][2]=fmaf(a2,w2,acc[2][2]); acc[2][3]=fmaf(a2,w3,acc[2][3]);
            acc[3][0]=fmaf(a3,w0,acc[3][0]); acc[3][1]=fmaf(a3,w1,acc[3][1]);
            acc[3][2]=fmaf(a3,w2,acc[3][2]); acc[3][3]=fmaf(a3,w3,acc[3][3]);
        }
    }
    #pragma unroll
    for (int i = 0; i < 4; ++i) {
        int r = r0 + ty * 4 + i;
        #pragma unroll
        for (int j = 0; j < 4; ++j)
            out[(size_t)r * C + c0 + tx * 4 + j] = acc[i][j] + bias[c0 + tx * 4 + j];
    }
}

// ---------------- lattice scan: ONE CTA per (b,dir), no cluster ----------------
// dynamic smem layout (bytes):
//   sWch  [128][256] uint (bf16x2)            0        131072
//   sWlc  [128][64]  uint                     131072   32768
//   sHh   [129][128] bf16                     163840   33024 (pad to 163840+33024=196864 -> align 196864)
//   fp32 scratch after 196864:
#define OFF_WLC   131072
#define OFF_HH    163840
#define OFF_F     196864
// float offsets within scratch (floats):
#define F_HPING 0      // [2][128]
#define F_GATES 256    // [512]
#define F_WV    768    // [384]
#define F_CWB   1152   // [128]
#define F_EW    1280   // [128]
#define F_EWC   1408   // [128]
#define F_XL    1536   // [128]
#define F_CBS   1664   // [128]
#define F_HBS   1792   // [128]
#define F_LGP   1920   // [128]
#define SCRATCH_FLOATS 2048
#define LAT_SMEM (OFF_F + SCRATCH_FLOATS * 4)   // 205056 B

__global__ void __launch_bounds__(256, 1)
lattice_kernel(
    const int* __restrict__ word_begin, const int* __restrict__ word_len,
    const int* __restrict__ seq_len,
    const float* __restrict__ f_Wwh, const float* __restrict__ r_Wwh)
{
    extern __shared__ char smraw[];
    unsigned* sWch = reinterpret_cast<unsigned*>(smraw);
    unsigned* sWlc = reinterpret_cast<unsigned*>(smraw + OFF_WLC);
    __nv_bfloat16* sHh = reinterpret_cast<__nv_bfloat16*>(smraw + OFF_HH);
    float* F = reinterpret_cast<float*>(smraw + OFF_F);
    float* hping = F + F_HPING;
    float* gates = F + F_GATES;
    float* wv    = F + F_WV;
    float* cwb   = F + F_CWB;
    float* ew    = F + F_EW;
    float* ewc   = F + F_EWC;
    float* xl    = F + F_XL;
    float* cbs   = F + F_CBS;
    float* hbs   = F + F_HBS;
    float* lgp   = F + F_LGP;
    __shared__ int s_wbeg[64], s_wend[64], s_evt[64];
    __shared__ unsigned s_m0, s_m1;

    int tid = threadIdx.x;
    int sid = blockIdx.x;            // (dir,b)
    int dir = sid >> 4, b = sid & 15;
    const float* Xg = g_Xg + (size_t)sid * 65536;
    const float* Xl = g_Xl + (size_t)sid * 16384;
    const float* Wg = g_Wg + (size_t)sid * 24576;
    const float* Wwh = dir ? r_Wwh : f_Wwh;
    const unsigned* Wchp = g_Wch_bf[dir];
    const unsigned* Wlcp = g_Wlc_bf[dir];
    float* chg = g_ch[sid];
    int Lb = seq_len[b];

    // load packed weights into smem
    for (int i = tid; i < 128 * 256; i += 256) sWch[i] = Wchp[i];
    for (int i = tid; i < 128 * 64; i += 256)  sWlc[i] = Wlcp[i];
    if (tid < 128) {
        hping[tid] = 0.f;
        sHh[tid] = __float2bfloat16(0.f);
        chg[tid] = 0.f;
    }
    if (tid < 64) {
        int bg = word_begin[b * 64 + tid];
        int ln = word_len[b * 64 + tid];
        int e = min(bg + ln, 127);
        int be, en;
        if (dir == 0) { be = bg; en = e; } else { be = 127 - e; en = 127 - bg; }
        s_wbeg[tid] = be;
        s_wend[tid] = (e < Lb) ? en : -1;
    }
    __syncthreads();

    for (int t = 0; t < 128; ++t) {
        int par = t & 1;
        const float* hprev = hping + par * 128;
        // word ballot
        if (tid < 64) {
            unsigned m = __ballot_sync(0xffffffffu, s_wend[tid] == t);
            if ((tid & 31) == 0) { if (tid < 32) s_m0 = m; else s_m1 = m; }
        }
        // ---- gate GEMV: thread c owns cols (2c, 2c+1), full k, bf16 weights ----
        {
            float2 xgv = reinterpret_cast<const float2*>(Xg + (size_t)t * 512)[tid];
            float a0 = xgv.x, a1 = xgv.y;
            float b0 = 0.f, b1 = 0.f;
            const unsigned* wp = sWch + tid;
            const float4* h4 = reinterpret_cast<const float4*>(hprev);
            #pragma unroll
            for (int q = 0; q < 32; ++q) {
                float4 hv = h4[q];
                unsigned u0 = wp[(4*q + 0) * 256];
                unsigned u1 = wp[(4*q + 1) * 256];
                unsigned u2 = wp[(4*q + 2) * 256];
                unsigned u3 = wp[(4*q + 3) * 256];
                float2 w0 = __bfloat1622float2(*reinterpret_cast<__nv_bfloat162*>(&u0));
                float2 w1 = __bfloat1622float2(*reinterpret_cast<__nv_bfloat162*>(&u1));
                float2 w2 = __bfloat1622float2(*reinterpret_cast<__nv_bfloat162*>(&u2));
                float2 w3 = __bfloat1622float2(*reinterpret_cast<__nv_bfloat162*>(&u3));
                a0 = fmaf(hv.x, w0.x, a0); a1 = fmaf(hv.x, w0.y, a1);
                b0 = fmaf(hv.y, w1.x, b0); b1 = fmaf(hv.y, w1.y, b1);
                a0 = fmaf(hv.z, w2.x, a0); a1 = fmaf(hv.z, w2.y, a1);
                b0 = fmaf(hv.w, w3.x, b0); b1 = fmaf(hv.w, w3.y, b1);
            }
            gates[2 * tid]     = a0 + b0;
            gates[2 * tid + 1] = a1 + b1;
        }
        __syncthreads();
        unsigned m0 = s_m0, m1 = s_m1;
        int nev = __popc(m0) + __popc(m1);

        // ---- word events ----
        if (nev) {
            if (tid < 64) {
                if (s_wend[tid] == t) {
                    int idx = (tid < 32) ? __popc(m0 & ((1u << tid) - 1u))
                                         : __popc(m0) + __popc(m1 & ((1u << (tid - 32)) - 1u));
                    s_evt[idx] = tid;
                }
            }
            if (tid < 128) {
                ew[tid] = 0.f; ewc[tid] = 0.f;
                xl[tid] = Xl[(size_t)t * 128 + tid];
            }
            __syncthreads();
            for (int r = 0; r < nev; ++r) {
                int w = s_evt[r];
                int bg = s_wbeg[w];
                // prefetch hb (smem bf16 -> fp32), cb (global), and start Wg loads
                if (tid < 128) {
                    hbs[tid] = __bfloat162float(sHh[bg * 128 + tid]);
                    cbs[tid] = chg[bg * 128 + tid];
                }
                float wg0 = 0.f, wg1 = 0.f;
                if (tid < 192) {
                    wg0 = Wg[(size_t)w * 384 + tid];
                    wg1 = Wg[(size_t)w * 384 + 192 + tid];
                }
                __syncthreads();
                // wvec GEMV from L2 (fp32 Wwh [128][384]): thread<192 cols (tid, tid+192)
                if (tid < 192) {
                    const float* wp = Wwh + tid;
                    float a0 = wg0, a1 = wg1, c0 = 0.f, c1 = 0.f;
                    #pragma unroll 4
                    for (int k = 0; k < 128; k += 2) {
                        float h0 = hbs[k], h1 = hbs[k + 1];
                        const float* row0 = wp + (size_t)k * 384;
                        const float* row1 = wp + (size_t)(k + 1) * 384;
                        a0 = fmaf(h0, row0[0],   a0);
                        a1 = fmaf(h0, row0[192], a1);
                        c0 = fmaf(h1, row1[0],   c0);
                        c1 = fmaf(h1, row1[192], c1);
                    }
                    wv[tid]       = a0 + c0;
                    wv[192 + tid] = a1 + c1;
                }
                __syncthreads();
                // cw
                if (tid < 128) {
                    float wi  = sigm(wv[tid]);
                    float wf  = sigm(wv[128 + tid]);
                    float wg2 = tanhf(wv[256 + tid]);
                    cwb[tid] = wf * cbs[tid] + wi * wg2;
                }
                __syncthreads();
                // lg GEMV from smem bf16 Wlc: thread c<64 owns cols (2c,2c+1)
                if (tid < 64) {
                    const unsigned* wp = sWlc + tid;
                    float a0 = 0.f, a1 = 0.f, b0 = 0.f, b1 = 0.f;
                    #pragma unroll 8
                    for (int k = 0; k < 128; k += 2) {
                        float cv0 = cwb[k], cv1 = cwb[k + 1];
                        unsigned u0 = wp[k * 64];
                        unsigned u1 = wp[(k + 1) * 64];
                        float2 w0 = __bfloat1622float2(*reinterpret_cast<__nv_bfloat162*>(&u0));
                        float2 w1 = __bfloat1622float2(*reinterpret_cast<__nv_bfloat162*>(&u1));
                        a0 = fmaf(cv0, w0.x, a0); a1 = fmaf(cv0, w0.y, a1);
                        b0 = fmaf(cv1, w1.x, b0); b1 = fmaf(cv1, w1.y, b1);
                    }
                    lgp[2 * tid]     = a0 + b0;
                    lgp[2 * tid + 1] = a1 + b1;
                }
                __syncthreads();
                if (tid < 128) {
                    float e = expf(sigm(lgp[tid] + xl[tid]));
                    ew[tid]  += e;
                    ewc[tid] += e * cwb[tid];
                }
                __syncthreads();
            }
        }
        // ---- pointwise ----
        if (tid < 128) {
            float gi = gates[tid], gf = gates[128 + tid], go = gates[256 + tid], gg = gates[384 + tid];
            float i_ = sigm(gi), f_ = sigm(gf), o_ = sigm(go), g_ = tanhf(gg);
            float cp = chg[t * 128 + tid];
            float hp = hping[par * 128 + tid];
            float ct;
            if (nev) { float ec = expf(i_); ct = (ec * g_ + ewc[tid]) / (ec + ew[tid]); }
            else     ct = f_ * cp + i_ * g_;
            float ht = o_ * tanhf(ct);
            bool v = dir ? (t >= 128 - Lb) : (t < Lb);
            float hn = v ? ht : hp;
            float cn = v ? ct : cp;
            hping[(par ^ 1) * 128 + tid] = hn;
            sHh[(t + 1) * 128 + tid] = __float2bfloat16(hn);
            chg[(t + 1) * 128 + tid] = cn;
            int pos = dir ? 127 - t : t;
            g_feats[((size_t)b * 128 + pos) * 256 + dir * 128 + tid] = v ? ht : 0.f;
        }
        __syncthreads();
    }
}

// ---------------- dense projection ----------------
__global__ void dense_kernel(const float* __restrict__ W, const float* __restrict__ bias)
{
    __shared__ float Wsm[8192];
    __shared__ float Fs[16 * 256];
    int tid = threadIdx.x;
    int row0 = blockIdx.x * 16;
    for (int i = tid; i < 8192; i += 256) Wsm[i] = W[i];
    for (int i = tid; i < 4096; i += 256) Fs[i] = g_feats[(size_t)row0 * 256 + i];
    __syncthreads();
    int l = tid & 31, rr = tid >> 5;
    float a0 = bias[l], a1 = a0;
    const float* f0 = Fs + rr * 256;
    const float* f1 = Fs + (rr + 8) * 256;
    #pragma unroll 8
    for (int q = 0; q < 256; ++q) {
        float w = Wsm[q * 32 + l];
        a0 = fmaf(f0[q], w, a0);
        a1 = fmaf(f1[q], w, a1);
    }
    g_logits[(size_t)(row0 + rr) * 32 + l]     = a0;
    g_logits[(size_t)(row0 + rr + 8) * 32 + l] = a1;
}

// ---------------- CRF ----------------
__global__ void crf_kernel(const int* __restrict__ label, const int* __restrict__ seq_len,
                           const float* __restrict__ crf_T)
{
    int b = blockIdx.x, l = threadIdx.x;
    __shared__ float Ts[1024], Es[1024];
    for (int i = l; i < 1024; i += 32) { float v = crf_T[i]; Ts[i] = v; Es[i] = expf(v); }
    __syncwarp();
    int L = seq_len[b];
    const float* lg = g_logits + (size_t)b * 4096;
    float alpha = lg[l];
    for (int t = 1; t < 128; ++t) {
        float m = alpha;
        for (int o = 16; o; o >>= 1) m = fmaxf(m, __shfl_xor_sync(0xffffffffu, m, o));
        float a = expf(alpha - m);
        float S = 0.f;
        #pragma unroll
        for (int i = 0; i < 32; ++i) {
            float ai = __shfl_sync(0xffffffffu, a, i);
            S = fmaf(ai, Es[i * 32 + l], S);
        }
        float nv = m + logf(S) + lg[t * 32 + l];
        if (t < L) alpha = nv;
    }
    float m = alpha;
    for (int o = 16; o; o >>= 1) m = fmaxf(m, __shfl_xor_sync(0xffffffffu, m, o));
    float e = expf(alpha - m);
    for (int o = 16; o; o >>= 1) e += __shfl_xor_sync(0xffffffffu, e, o);
    float logZ = m + logf(e);
    float gsum = 0.f;
    for (int t = l; t < 128; t += 32) {
        if (t < L) {
            int lab = label[b * 128 + t];
            gsum += lg[t * 32 + lab];
            if (t >= 1) gsum += Ts[label[b * 128 + t - 1] * 32 + lab];
        }
    }
    for (int o = 16; o; o >>= 1) gsum += __shfl_xor_sync(0xffffffffu, gsum, o);
    if (l == 0) g_res[b] = logZ - gsum;
}

__global__ void finalize_kernel(float* out)
{
    float s = 0.f;
    #pragma unroll
    for (int b = 0; b < 16; ++b) s += g_res[b];
    out[0] = s * 0.0625f;
}

// ---------------- launch ----------------
extern "C" void kernel_launch(void* const* d_in, const int* in_sizes, int n_in,
                              void* d_out, int out_size)
{
    const int*   char_ids    = (const int*)d_in[0];
    const int*   kb_word_ids = (const int*)d_in[1];
    const int*   word_begin  = (const int*)d_in[2];
    const int*   word_len    = (const int*)d_in[3];
    const int*   label       = (const int*)d_in[4];
    const int*   seq_len     = (const int*)d_in[5];
    const float* char_emb    = (const float*)d_in[6];
    const float* kb_emb      = (const float*)d_in[7];
    const float* dense_W     = (const float*)d_in[8];
    const float* dense_b     = (const float*)d_in[9];
    const float* crf_T       = (const float*)d_in[10];
    const float* f_Wcx = (const float*)d_in[11];
    const float* f_Wch = (const float*)d_in[12];
    const float* f_bc  = (const float*)d_in[13];
    const float* f_Wwx = (const float*)d_in[14];
    const float* f_Wwh = (const float*)d_in[15];
    const float* f_bw  = (const float*)d_in[16];
    const float* f_Wlx = (const float*)d_in[17];
    const float* f_Wlc = (const float*)d_in[18];
    const float* f_bl  = (const float*)d_in[19];
    const float* r_Wcx = (const float*)d_in[20];
    const float* r_Wch = (const float*)d_in[21];
    const float* r_bc  = (const float*)d_in[22];
    const float* r_Wwx = (const float*)d_in[23];
    const float* r_Wwh = (const float*)d_in[24];
    const float* r_bw  = (const float*)d_in[25];
    const float* r_Wlx = (const float*)d_in[26];
    const float* r_Wlc = (const float*)d_in[27];
    const float* r_bl  = (const float*)d_in[28];

    cudaFuncSetAttribute(lattice_kernel, cudaFuncAttributeMaxDynamicSharedMemorySize, LAT_SMEM);

    convert_weights_kernel<<<256, 256>>>(f_Wch, r_Wch, f_Wlc, r_Wlc);
    gemm_gather_kernel<<<dim3(8, 64), 256>>>(0, char_ids, kb_word_ids, char_emb, kb_emb,
                                             f_Wcx, r_Wcx, f_bc, r_bc, 512, 2048);
    gemm_gather_kernel<<<dim3(2, 64), 256>>>(1, char_ids, kb_word_ids, char_emb, kb_emb,
                                             f_Wlx, r_Wlx, f_bl, r_bl, 128, 2048);
    gemm_gather_kernel<<<dim3(6, 32), 256>>>(2, char_ids, kb_word_ids, char_emb, kb_emb,
                                             f_Wwx, r_Wwx, f_bw, r_bw, 384, 1024);

    lattice_kernel<<<32, 256, LAT_SMEM>>>(word_begin, word_len, seq_len, f_Wwh, r_Wwh);

    dense_kernel<<<128, 256>>>(dense_W, dense_b);
    crf_kernel<<<16, 32>>>(label, seq_len, crf_T);
    finalize_kernel<<<1, 1>>>((float*)d_out);
}